// round 17
// baseline (speedup 1.0000x reference)
#include <cuda_runtime.h>
#include <cuda_fp16.h>
#include <cstdint>

#define BSZ  8
#define LSZ  2048
#define DMSZ 1024
#define DHSZ 1024
#define MSZ  (BSZ * LSZ)   // 16384
#define NCH  64            // scan chunks
#define CHL  (LSZ / NCH)   // 32 steps per chunk
#define NCHN (BSZ * DHSZ)  // 8192 channels

// ---------------- scratch (__device__ globals; allocation-free rule) -------
__device__ __half g_xh[(size_t)MSZ * DMSZ];     // x fp16
__device__ __half g_dwh[DHSZ * DMSZ];
__device__ __half g_Bwh[DHSZ * DMSZ];
__device__ __half g_Dwh[DMSZ * DMSZ];
__device__ __half g_Cwh[DMSZ * DHSZ];
__device__ __half g_Hq[(size_t)MSZ * DHSZ];     // h / s_row, fp16
__device__ float  g_Srow[MSZ];                  // per-row pow2 scale
__device__ float  g_Abar[(size_t)MSZ * DHSZ];
__device__ float  g_Bbar[(size_t)MSZ * DHSZ];
__device__ float  g_pA[NCH * NCHN];             // chunk summaries
__device__ float  g_pB[NCH * NCHN];
__device__ float  g_h0[NCH * NCHN];             // chunk-start states

// ---------------- helpers --------------------------------------------------
__device__ __forceinline__ uint32_t smem_u32(const void* p) {
    uint32_t a;
    asm("{ .reg .u64 t; cvta.to.shared.u64 t, %1; cvt.u32.u64 %0, t; }"
        : "=r"(a) : "l"(p));
    return a;
}

// 16-bit tiles: rows of 32 elems = 64B = 4 chunks of 16B; chunk ^= (row>>1)&3.
__device__ __forceinline__ uint32_t sw_chunk_off(int r, int c) {
    return (uint32_t)(((r << 2) | (c ^ ((r >> 1) & 3))) << 4);
}

__device__ __forceinline__ void ldsm4(uint32_t* d, uint32_t addr) {
    asm volatile("ldmatrix.sync.aligned.m8n8.x4.shared.b16 {%0,%1,%2,%3}, [%4];"
                 : "=r"(d[0]), "=r"(d[1]), "=r"(d[2]), "=r"(d[3]) : "r"(addr));
}

__device__ __forceinline__ void mma_f16(float* c, const uint32_t* a, const uint32_t* b) {
    asm volatile(
        "mma.sync.aligned.m16n8k16.row.col.f32.f16.f16.f32 "
        "{%0,%1,%2,%3}, {%4,%5,%6,%7}, {%8,%9}, {%0,%1,%2,%3};"
        : "+f"(c[0]), "+f"(c[1]), "+f"(c[2]), "+f"(c[3])
        : "r"(a[0]), "r"(a[1]), "r"(a[2]), "r"(a[3]), "r"(b[0]), "r"(b[1]));
}

__device__ __forceinline__ uint32_t addrA(uint32_t sbase, int mrow, int c0) {
    int l = threadIdx.x & 31;
    int r = mrow + (l & 15);
    int c = c0 + (l >> 4);
    return sbase + sw_chunk_off(r, c);
}
__device__ __forceinline__ uint32_t addrB(uint32_t sbase, int nrow, int c0) {
    int l = threadIdx.x & 31;
    int r = nrow + (l & 7) + ((l >> 4) << 3);
    int c = c0 + ((l >> 3) & 1);
    return sbase + sw_chunk_off(r, c);
}

// 16-bit tile loader: ROWS x 32 elems (64B rows) at (row0, kb).
template <int ROWS>
__device__ __forceinline__ void load_tile_async(uint32_t sbase,
                                                const void* __restrict__ g,
                                                int row0, int kb)
{
    int t = threadIdx.x;
    const char* gb = (const char*)g + ((size_t)row0 * 1024 + kb) * 2;
#pragma unroll
    for (int i = 0; i < (ROWS * 4) / 256; i++) {
        int idx = i * 256 + t;
        int r = idx >> 2;
        int c = idx & 3;
        const char* src = gb + (size_t)r * 2048 + c * 16;
        uint32_t dst = sbase + sw_chunk_off(r, c);
        asm volatile("cp.async.cg.shared.global [%0], [%1], 16;"
                     :: "r"(dst), "l"(src) : "memory");
    }
}
#define CP_COMMIT()  asm volatile("cp.async.commit_group;" ::: "memory")
#define CP_WAIT(n)   asm volatile("cp.async.wait_group %0;" :: "n"(n) : "memory")

// ---------------- prep kernels ---------------------------------------------
__global__ __launch_bounds__(256) void convert_x_kernel(
    const float* __restrict__ src, __half* __restrict__ dst, int n4)
{
    int i = blockIdx.x * 256 + threadIdx.x;
    if (i >= n4) return;
    float4 v = ((const float4*)src)[i];
    __half2* dp = (__half2*)(dst + (size_t)i * 4);
    dp[0] = __halves2half2(__float2half_rn(v.x), __float2half_rn(v.y));
    dp[1] = __halves2half2(__float2half_rn(v.z), __float2half_rn(v.w));
}

// dw, Bw, Dw, Cw -> single fp16 (blockIdx.y selects)
__global__ __launch_bounds__(256) void convert_w16_kernel(
    const float* __restrict__ s0, const float* __restrict__ s1,
    const float* __restrict__ s2, const float* __restrict__ s3,
    __half* __restrict__ d0, __half* __restrict__ d1,
    __half* __restrict__ d2, __half* __restrict__ d3)
{
    const float* s;
    __half* d;
    switch (blockIdx.y) {
        case 0:  s = s0; d = d0; break;
        case 1:  s = s1; d = d1; break;
        case 2:  s = s2; d = d2; break;
        default: s = s3; d = d3; break;
    }
    int i = blockIdx.x * 256 + threadIdx.x;
    float4 v = ((const float4*)s)[i];
    __half2* dp = (__half2*)(d + (size_t)i * 4);
    dp[0] = __halves2half2(__float2half_rn(v.x), __float2half_rn(v.y));
    dp[1] = __halves2half2(__float2half_rn(v.z), __float2half_rn(v.w));
}

// ---------------- kernel 1: dual GEMM (x@dw^T, x@Bw^T) + SSM epilogue ------
// fp16 single-term. CTA 128x64; 8 warps 4m x 2n; warp 32x32; BK=32; 4-stage.
// Stage (16KB): xh 0, dw 8192, Bw 12288.
__global__ __launch_bounds__(256, 2)
void gemm1_kernel(const float* __restrict__ dbias, const float* __restrict__ Bb,
                  const float* __restrict__ Avec)
{
    extern __shared__ char smem[];
    uint32_t sb = smem_u32(smem);
    const int t = threadIdx.x, wid = t >> 5, lane = t & 31;
    const int m0 = blockIdx.y * 128, n0 = blockIdx.x * 64;
    const int wm = (wid & 3) * 32;
    const int wn = (wid >> 2) * 32;

    float acc1[2][4][4], acc2[2][4][4];
#pragma unroll
    for (int i = 0; i < 2; i++)
#pragma unroll
        for (int j = 0; j < 4; j++)
#pragma unroll
            for (int q = 0; q < 4; q++) { acc1[i][j][q] = 0.f; acc2[i][j][q] = 0.f; }

    auto issue_stage = [&](int s, int kidx) {
        uint32_t st = sb + s * 16384;
        int kb = kidx * 32;
        load_tile_async<128>(st,          g_xh,  m0, kb);
        load_tile_async<64> (st + 8192,   g_dwh, n0, kb);
        load_tile_async<64> (st + 12288,  g_Bwh, n0, kb);
        CP_COMMIT();
    };
    issue_stage(0, 0);
    issue_stage(1, 1);
    issue_stage(2, 2);

    const int K = 32;
    for (int k = 0; k < K; k++) {
        if (k < K - 2)       CP_WAIT(2);
        else if (k == K - 2) CP_WAIT(1);
        else                 CP_WAIT(0);
        __syncthreads();
        if (k + 3 < K) issue_stage((k + 3) & 3, k + 3);

        uint32_t st = sb + (k & 3) * 16384;
#pragma unroll
        for (int kk = 0; kk < 2; kk++) {
            int c0 = kk * 2;
            uint32_t ah[2][4];
#pragma unroll
            for (int mt = 0; mt < 2; mt++)
                ldsm4(ah[mt], addrA(st, wm + mt * 16, c0));
            uint32_t b1[8], b2[8];
            ldsm4(b1,     addrB(st + 8192,  wn,      c0));
            ldsm4(b1 + 4, addrB(st + 8192,  wn + 16, c0));
            ldsm4(b2,     addrB(st + 12288, wn,      c0));
            ldsm4(b2 + 4, addrB(st + 12288, wn + 16, c0));
#pragma unroll
            for (int mt = 0; mt < 2; mt++)
#pragma unroll
                for (int nt = 0; nt < 4; nt++) {
                    mma_f16(acc1[mt][nt], ah[mt], &b1[nt * 2]);
                    mma_f16(acc2[mt][nt], ah[mt], &b2[nt * 2]);
                }
        }
    }

    // epilogue
    const int lr = lane >> 2, lc = lane & 3;
    float dbv[4][2], avv[4][2], bbv[4][2];
#pragma unroll
    for (int nt = 0; nt < 4; nt++)
#pragma unroll
        for (int j = 0; j < 2; j++) {
            int n = n0 + wn + nt * 8 + lc * 2 + j;
            dbv[nt][j] = __ldg(&dbias[n]);
            avv[nt][j] = __ldg(&Avec[n]);
            bbv[nt][j] = __ldg(&Bb[n]);
        }
#pragma unroll
    for (int mt = 0; mt < 2; mt++)
#pragma unroll
        for (int half = 0; half < 2; half++) {
            int m = m0 + wm + mt * 16 + half * 8 + lr;
            size_t rowo = (size_t)m * DHSZ;
#pragma unroll
            for (int nt = 0; nt < 4; nt++) {
                int n = n0 + wn + nt * 8 + lc * 2;
                float2 oa, ob;
#pragma unroll
                for (int j = 0; j < 2; j++) {
                    float t1 = acc1[mt][nt][half * 2 + j] + dbv[nt][j];
                    float e = __expf(-fabsf(t1));
                    float delta = fmaxf(t1, 0.f) + __logf(1.f + e);
                    float a = __expf(delta * avv[nt][j]);
                    float b = delta * (acc2[mt][nt][half * 2 + j] + bbv[nt][j]);
                    if (j == 0) { oa.x = a; ob.x = b; } else { oa.y = a; ob.y = b; }
                }
                *(float2*)&g_Abar[rowo + n] = oa;
                *(float2*)&g_Bbar[rowo + n] = ob;
            }
        }
}

// ---------------- scan phase A: per-(channel, chunk) summaries -------------
// Thread (c, ch): over CHL steps compute prodA = prod(a), partB = scan(b|h0=0).
__global__ __launch_bounds__(256) void scanA_kernel()
{
    int c  = blockIdx.x * 256 + threadIdx.x;   // 0..8191
    int ch = blockIdx.y;                        // 0..NCH-1
    int b = c >> 10;
    int h = c & (DHSZ - 1);
    size_t base = (size_t)b * LSZ * DHSZ + (size_t)ch * CHL * DHSZ + h;

    float pa = 1.f, hb = 0.f;
    for (int l0 = 0; l0 < CHL; l0 += 16) {
        float av[16], bv[16];
#pragma unroll
        for (int u = 0; u < 16; u++) {
            size_t o = base + (size_t)(l0 + u) * DHSZ;
            av[u] = g_Abar[o];
            bv[u] = g_Bbar[o];
        }
#pragma unroll
        for (int u = 0; u < 16; u++) {
            hb = fmaf(av[u], hb, bv[u]);
            pa *= av[u];
        }
    }
    g_pA[ch * NCHN + c] = pa;
    g_pB[ch * NCHN + c] = hb;
}

// ---------------- scan phase B: compose summaries -> chunk-start states ----
__global__ __launch_bounds__(256) void scanB_kernel()
{
    int c = blockIdx.x * 256 + threadIdx.x;    // 0..8191
    float h0 = 0.f;
#pragma unroll
    for (int ch = 0; ch < NCH; ch++) {
        g_h0[ch * NCHN + c] = h0;
        h0 = fmaf(g_pA[ch * NCHN + c], h0, g_pB[ch * NCHN + c]);
    }
}

// ---------------- scan phase C (fused quantize): h -> Hq fp16 + Srow -------
// Block (ch, b): 256 threads, thread t owns channels 4t..4t+3. For each
// l in chunk: h = a*h + b across the FULL row (1024 channels in-block),
// block-reduce rowmax, pow2 scale, write Hq + Srow. g_H eliminated.
__global__ __launch_bounds__(256) void scanCq_kernel()
{
    int ch = blockIdx.x;                       // 0..NCH-1
    int b  = blockIdx.y;                       // 0..BSZ-1
    int t  = threadIdx.x;
    int lane = t & 31, wid = t >> 5;

    __shared__ float wmx[2][8];

    // chunk-start state for this thread's 4 channels
    float4 h = *(const float4*)&g_h0[ch * NCHN + b * DHSZ + t * 4];

    size_t mbase = (size_t)b * LSZ + (size_t)ch * CHL;   // first row index
    size_t ebase = mbase * DHSZ + t * 4;                  // element offset

    float4 a4 = *(const float4*)&g_Abar[ebase];
    float4 b4 = *(const float4*)&g_Bbar[ebase];

    for (int l = 0; l < CHL; l++) {
        float4 an, bn;
        if (l + 1 < CHL) {
            an = *(const float4*)&g_Abar[ebase + (size_t)(l + 1) * DHSZ];
            bn = *(const float4*)&g_Bbar[ebase + (size_t)(l + 1) * DHSZ];
        }
        h.x = fmaf(a4.x, h.x, b4.x);
        h.y = fmaf(a4.y, h.y, b4.y);
        h.z = fmaf(a4.z, h.z, b4.z);
        h.w = fmaf(a4.w, h.w, b4.w);

        float mx = fmaxf(fmaxf(fabsf(h.x), fabsf(h.y)), fmaxf(fabsf(h.z), fabsf(h.w)));
#pragma unroll
        for (int o = 16; o; o >>= 1)
            mx = fmaxf(mx, __shfl_xor_sync(0xFFFFFFFFu, mx, o));
        int ph = l & 1;
        if (lane == 0) wmx[ph][wid] = mx;
        __syncthreads();
        mx = fmaxf(fmaxf(fmaxf(wmx[ph][0], wmx[ph][1]), fmaxf(wmx[ph][2], wmx[ph][3])),
                   fmaxf(fmaxf(wmx[ph][4], wmx[ph][5]), fmaxf(wmx[ph][6], wmx[ph][7])));

        uint32_t bits = __float_as_uint(mx);
        uint32_t e = (bits & 0x7f800000u) + ((bits & 0x007fffffu) ? 0x00800000u : 0u);
        if (mx == 0.f) e = 0x3f800000u;
        float s = __uint_as_float(e);
        float inv = 1.f / s;                   // exact (pow2)
        if (t == 0) g_Srow[mbase + l] = s;

        __half2* dst = (__half2*)&g_Hq[ebase + (size_t)l * DHSZ];
        dst[0] = __halves2half2(__float2half_rn(h.x * inv), __float2half_rn(h.y * inv));
        dst[1] = __halves2half2(__float2half_rn(h.z * inv), __float2half_rn(h.w * inv));

        a4 = an; b4 = bn;
    }
}

// ---------------- kernel 3: out = s_m*(Hq@Cw^T) + x@Dw^T + Cb + Db ---------
// All fp16. CTA 128x128; 8 warps 2m x 4n; warp 64x32; BK=32; 4-stage pipe.
// Stage (16KB): A 0, B 8192. Pass1 k<32: (Hq, Cw); pass2: (xh, Dw).
// At k==32 boundary, acc *= Srow (per-row pow2 scale).
__global__ __launch_bounds__(256, 2)
void gemm3_kernel(const float* __restrict__ Cb, const float* __restrict__ Db,
                  float* __restrict__ out)
{
    extern __shared__ char smem[];
    uint32_t sb = smem_u32(smem);
    const int t = threadIdx.x, wid = t >> 5, lane = t & 31;
    const int m0 = blockIdx.y * 128, n0 = blockIdx.x * 128;
    const int wm = (wid & 1) * 64;
    const int wn = (wid >> 1) * 32;
    const int lr = lane >> 2, lc = lane & 3;

    float acc[4][4][4];
#pragma unroll
    for (int i = 0; i < 4; i++)
#pragma unroll
        for (int j = 0; j < 4; j++)
#pragma unroll
            for (int q = 0; q < 4; q++) acc[i][j][q] = 0.f;

    auto issue_stage = [&](int s, int kidx) {
        uint32_t st = sb + s * 16384;
        int kb = (kidx & 31) * 32;
        if (kidx < 32) {
            load_tile_async<128>(st,         g_Hq,  m0, kb);
            load_tile_async<128>(st + 8192,  g_Cwh, n0, kb);
        } else {
            load_tile_async<128>(st,         g_xh,  m0, kb);
            load_tile_async<128>(st + 8192,  g_Dwh, n0, kb);
        }
        CP_COMMIT();
    };
    issue_stage(0, 0);
    issue_stage(1, 1);
    issue_stage(2, 2);

    const int K = 64;
    for (int k = 0; k < K; k++) {
        if (k < K - 2)       CP_WAIT(2);
        else if (k == K - 2) CP_WAIT(1);
        else                 CP_WAIT(0);
        __syncthreads();
        if (k + 3 < K) issue_stage((k + 3) & 3, k + 3);

        if (k == 32) {
            // scale pass-1 accumulators by per-row pow2 s_m
#pragma unroll
            for (int mt = 0; mt < 4; mt++)
#pragma unroll
                for (int half = 0; half < 2; half++) {
                    float s = __ldg(&g_Srow[m0 + wm + mt * 16 + half * 8 + lr]);
#pragma unroll
                    for (int nt = 0; nt < 4; nt++) {
                        acc[mt][nt][half * 2 + 0] *= s;
                        acc[mt][nt][half * 2 + 1] *= s;
                    }
                }
        }

        uint32_t st = sb + (k & 3) * 16384;
#pragma unroll
        for (int kk = 0; kk < 2; kk++) {
            int c0 = kk * 2;
            uint32_t ah[4][4];
#pragma unroll
            for (int mt = 0; mt < 4; mt++)
                ldsm4(ah[mt], addrA(st, wm + mt * 16, c0));
            uint32_t bh[8];
            ldsm4(bh,     addrB(st + 8192, wn,      c0));
            ldsm4(bh + 4, addrB(st + 8192, wn + 16, c0));
#pragma unroll
            for (int mt = 0; mt < 4; mt++)
#pragma unroll
                for (int nt = 0; nt < 4; nt++)
                    mma_f16(acc[mt][nt], ah[mt], &bh[nt * 2]);
        }
    }

    float biasv[4][2];
#pragma unroll
    for (int nt = 0; nt < 4; nt++)
#pragma unroll
        for (int j = 0; j < 2; j++) {
            int n = n0 + wn + nt * 8 + lc * 2 + j;
            biasv[nt][j] = __ldg(&Cb[n]) + __ldg(&Db[n]);
        }
#pragma unroll
    for (int mt = 0; mt < 4; mt++)
#pragma unroll
        for (int half = 0; half < 2; half++) {
            int m = m0 + wm + mt * 16 + half * 8 + lr;
            size_t rowo = (size_t)m * DMSZ;
#pragma unroll
            for (int nt = 0; nt < 4; nt++) {
                int n = n0 + wn + nt * 8 + lc * 2;
                float2 o;
                o.x = acc[mt][nt][half * 2 + 0] + biasv[nt][0];
                o.y = acc[mt][nt][half * 2 + 1] + biasv[nt][1];
                *(float2*)&out[rowo + n] = o;
            }
        }
}

// ---------------- launch ---------------------------------------------------
// Inputs: 0:x 1:A 2:Bw 3:Bb 4:Cw 5:Cb 6:Dw 7:Db 8:dw 9:db
extern "C" void kernel_launch(void* const* d_in, const int* in_sizes, int n_in,
                              void* d_out, int out_size)
{
    const float* x    = (const float*)d_in[0];
    const float* Avec = (const float*)d_in[1];
    const float* Bw   = (const float*)d_in[2];
    const float* Bb   = (const float*)d_in[3];
    const float* Cw   = (const float*)d_in[4];
    const float* Cb   = (const float*)d_in[5];
    const float* Dw   = (const float*)d_in[6];
    const float* Db   = (const float*)d_in[7];
    const float* dw   = (const float*)d_in[8];
    const float* db   = (const float*)d_in[9];
    float* out = (float*)d_out;

    void *xh, *dwh, *bwh, *Dwh, *cwh;
    cudaGetSymbolAddress(&xh, g_xh);
    cudaGetSymbolAddress(&dwh, g_dwh);   cudaGetSymbolAddress(&bwh, g_Bwh);
    cudaGetSymbolAddress(&Dwh, g_Dwh);   cudaGetSymbolAddress(&cwh, g_Cwh);

    cudaFuncSetAttribute(gemm1_kernel, cudaFuncAttributeMaxDynamicSharedMemorySize, 65536);
    cudaFuncSetAttribute(gemm3_kernel, cudaFuncAttributeMaxDynamicSharedMemorySize, 65536);

    int nx4 = (MSZ * DMSZ) / 4;       // 4,194,304
    int nw4 = (DHSZ * DMSZ) / 4;      // 262,144
    convert_x_kernel<<<nx4 / 256, 256>>>(x, (__half*)xh, nx4);
    dim3 gw(nw4 / 256, 4);
    convert_w16_kernel<<<gw, 256>>>(dw, Bw, Dw, Cw,
                                    (__half*)dwh, (__half*)bwh, (__half*)Dwh, (__half*)cwh);

    dim3 g1(DHSZ / 64, MSZ / 128);    // (16, 128)
    gemm1_kernel<<<g1, 256, 65536>>>(db, Bb, Avec);

    dim3 gs(NCHN / 256, NCH);         // (32, 64)
    scanA_kernel<<<gs, 256>>>();
    scanB_kernel<<<NCHN / 256, 256>>>();
    dim3 gc(NCH, BSZ);                // (64, 8)
    scanCq_kernel<<<gc, 256>>>();

    dim3 g3(DMSZ / 128, MSZ / 128);   // (8, 128)
    gemm3_kernel<<<g3, 256, 65536>>>(Cb, Db, out);
}